// round 14
// baseline (speedup 1.0000x reference)
#include <cuda_runtime.h>
#include <cuda_fp16.h>
#include <cstdint>

// ---------------- problem dims ----------------
#define M_DIM 4096
#define K_DIM 4096
#define N_DIM 11008

#define TILE_M 128
#define TILE_N 128
#define TILE_K 64
#define STAGES 4
#define K_CHUNKS (K_DIM / TILE_K)      // 64
#define M_TILES (M_DIM / TILE_M)       // 32
#define N_TILES (N_DIM / TILE_N)       // 86
#define NTILES  (M_TILES * N_TILES)    // 2752

#define A_CHUNK_HALFS (TILE_M * TILE_K)       // 8192
#define A_STAGE_BYTES (A_CHUNK_HALFS * 2)     // 16384
#define B_CHUNK_WORDS 1024                    // packed int4: 128n x 64k / 8 per word
#define B_STAGE_BYTES (B_CHUNK_WORDS * 4)     // 4096
#define CHUNK_BYTES   (A_STAGE_BYTES + B_STAGE_BYTES)

#define SM_FULL  64
#define SM_EMPTY 128
#define SM_A     1024
#define SM_B     (SM_A + STAGES * A_STAGE_BYTES)       // 66560
#define SMEM_BYTES (SM_B + STAGES * B_STAGE_BYTES)     // 82944 (x2 CTAs = 165888)

// ---------------- scratch (device globals; allocation forbidden) ----------------
// A fragment-major: [mblock(32)][kchunk64(64)][bi(32)][lane(32)] uint4
//   bi = mtile(0..7)*4 + kstep(0..3).  lane's uint4 = a0..a3 of m16n8k16
//   (r=lane>>2, c2=(lane&3)*2):
//   (r,c2),(r,c2+1) | (r+8,c2),(r+8,c2+1) | (r,c2+8),(r,c2+9) | (r+8,c2+8),(r+8,c2+9)
__device__ __half g_xs[(size_t)M_DIM * K_DIM];
// B packed int4, decode-ready: [nblock(86)][kchunk64(64)][p(16)][kh(2)][lane(32)] uint32
//   Source: packed_w is (N, K/2) int32, ONE byte per element (low 8 bits).
//   Byte for (row n, k-pair i) = pw[n*2048 + i]; lo nibble = k=2i, hi = k=2i+1.
//   Word (p,kh,lane), row n=p*8+(lane>>2), bytes i = kc*32 + kh*16 + 4t + (lane&3):
//     bits[4t+3:4t]       = lo nibble of byte t   (k = kh*32 + 8t + c2)
//     bits[16+4t+3:16+4t] = hi nibble of byte t   (k = kh*32 + 8t + c2 + 1)
//   all nibbles ^8.  Decode: dec4(w,4t) = half2(k, k+1) values == R9 fp16 B exactly.
__device__ uint32_t g_wp[(size_t)N_DIM * K_DIM / 8];
__device__ float g_cp[(size_t)128 * M_DIM];   // partial c: [kc32][m]
__device__ float g_c[M_DIM];                  // c[m] = sum_k x[m,k]*s[g]*zp[g]

// ---------------- PTX helpers (generic features only) ----------------
__device__ __forceinline__ uint32_t smem_u32(const void* p) {
    uint32_t a;
    asm("{ .reg .u64 t; cvta.to.shared.u64 t, %1; cvt.u32.u64 %0, t; }" : "=r"(a) : "l"(p));
    return a;
}

#define MBAR_INIT(addr, cnt) \
    asm volatile("mbarrier.init.shared.b64 [%0], %1;" :: "r"(addr), "r"((uint32_t)(cnt)) : "memory")
#define MBAR_EXPECT_TX(addr, bytes) \
    asm volatile("mbarrier.arrive.expect_tx.shared.b64 _, [%0], %1;" :: "r"(addr), "r"((uint32_t)(bytes)) : "memory")
#define MBAR_ARRIVE(addr) \
    asm volatile("mbarrier.arrive.shared.b64 _, [%0];" :: "r"(addr) : "memory")

#define MBAR_WAIT(addr, parity) do {                                              \
    uint32_t _m = (addr); uint32_t _p = (parity); uint32_t _done;                 \
    asm volatile("{ .reg .pred p;"                                                \
        " mbarrier.try_wait.parity.shared.b64 p, [%1], %2;"                       \
        " selp.b32 %0, 1, 0, p; }" : "=r"(_done) : "r"(_m), "r"(_p) : "memory");  \
    if (!_done) {                                                                 \
        asm volatile("{ .reg .pred P1;"                                           \
            " WL_%=:"                                                             \
            " mbarrier.try_wait.parity.shared.b64 P1, [%0], %1;"                  \
            " @P1 bra.uni WD_%=;"                                                 \
            " bra.uni WL_%=;"                                                     \
            " WD_%=: }" :: "r"(_m), "r"(_p) : "memory");                          \
    }                                                                             \
} while (0)

#define BULK_G2S(dst, src, bytes, mbar)                                           \
    asm volatile("cp.async.bulk.shared::cluster.global.mbarrier::complete_tx::bytes " \
                 "[%0], [%1], %2, [%3];"                                          \
                 :: "r"(dst), "l"(src), "r"((uint32_t)(bytes)), "r"(mbar) : "memory")

#define MMA_F16(acc, au, b0, b1)                                                  \
    asm volatile("mma.sync.aligned.m16n8k16.row.col.f32.f16.f16.f32 "             \
        "{%0,%1,%2,%3}, {%4,%5,%6,%7}, {%8,%9}, {%0,%1,%2,%3};"                   \
        : "+f"((acc)[0]), "+f"((acc)[1]), "+f"((acc)[2]), "+f"((acc)[3])          \
        : "r"((au)[0]), "r"((au)[1]), "r"((au)[2]), "r"((au)[3]),                 \
          "r"(b0), "r"(b1))

__device__ __forceinline__ uint32_t h2u(float lo, float hi) {
    __half2 h = __floats2half2_rn(lo, hi);
    return *reinterpret_cast<uint32_t*>(&h);
}

// decode one nibble-slice: ((w>>s) & 0x000F000F) | 0x64006400, then -1032 per half
__device__ __forceinline__ uint32_t dec4(uint32_t w, int s) {
    uint32_t r = ((w >> s) & 0x000F000Fu) | 0x64006400u;
    __half2 h = *reinterpret_cast<__half2*>(&r);
    const uint32_t cu = 0x64086408u;                  // half2(1032, 1032)
    __half2 c = *reinterpret_cast<const __half2*>(&cu);
    __half2 v = __hsub2(h, c);
    return *reinterpret_cast<uint32_t*>(&v);
}

// ---------------- prep: x' = fp16(x*s) frag-major + partial c ----------------
__global__ void __launch_bounds__(256) prep_x_kernel(const float* __restrict__ x,
                                                     const float* __restrict__ scales,
                                                     const float* __restrict__ zps) {
    const int kc = blockIdx.x;             // 32-k granule 0..127
    const int mb = blockIdx.y;
    const int tid = threadIdx.x;
    __shared__ float sm[TILE_M * 33];      // 128x32, padded (conflict-free rows)

    const float s = scales[kc >> 1];       // group = 64 elems = 2 granules
    const float* xsrc = x + (size_t)mb * 128 * K_DIM + kc * 32;
#pragma unroll
    for (int i = 0; i < 16; i++) {
        int idx = tid + i * 256;
        int row = idx >> 5, col = idx & 31;
        sm[row * 33 + col] = xsrc[(size_t)row * K_DIM + col] * s;
    }
    __syncthreads();

    if (tid < 128) {
        float a = 0.f;
#pragma unroll
        for (int i = 0; i < 32; i++) a += sm[tid * 33 + i];
        g_cp[(size_t)kc * M_DIM + mb * 128 + tid] = a * zps[kc >> 1];
    }

    const int lane = tid & 31, w = tid >> 5;
    uint4* dst = reinterpret_cast<uint4*>(
        g_xs + ((size_t)mb * K_CHUNKS + (kc >> 1)) * A_CHUNK_HALFS);
    const int r = lane >> 2, c2 = (lane & 3) * 2;
    const int khalf = (kc & 1) * 2;        // kstep offset within 64-k chunk
#pragma unroll
    for (int i = 0; i < 2; i++) {
        int blk = w * 2 + i;               // 0..15
        int mt = blk >> 1, ks = blk & 1;
        int rr = mt * 16 + r;
        int k0 = ks * 16 + c2;
        uint4 v;
        v.x = h2u(sm[rr * 33 + k0],           sm[rr * 33 + k0 + 1]);
        v.y = h2u(sm[(rr + 8) * 33 + k0],     sm[(rr + 8) * 33 + k0 + 1]);
        v.z = h2u(sm[rr * 33 + k0 + 8],       sm[rr * 33 + k0 + 9]);
        v.w = h2u(sm[(rr + 8) * 33 + k0 + 8], sm[(rr + 8) * 33 + k0 + 9]);
        dst[(mt * 4 + khalf + ks) * 32 + lane] = v;
    }
}

// ---------------- prep: reduce partial c (fixed order -> deterministic) ----------------
__global__ void __launch_bounds__(256) reduce_c_kernel() {
    const int m = blockIdx.x * 256 + threadIdx.x;
    float a = 0.f;
#pragma unroll 8
    for (int kc = 0; kc < 128; kc++) a += g_cp[(size_t)kc * M_DIM + m];
    g_c[m] = a;
}

// ---------------- prep: repack int4 into decode-ready words ----------------
// packed_w: (N, K/2) int32, ONE byte per element. Row stride = 2048 int32.
__global__ void __launch_bounds__(256) prep_wp_kernel(const int* __restrict__ pw) {
    const int kc = blockIdx.x;             // 64-k chunk 0..63
    const int nb = blockIdx.y;             // nblock 0..85
    const int tid = threadIdx.x;
    __shared__ uint8_t smb[128 * 32];      // 128 rows x 32 bytes (the chunk's k-pairs)

    // load: rows nb*128..+127, int32 elements kc*32..+31 of each row; keep low byte
#pragma unroll
    for (int i = 0; i < 4; i++) {
        int idx = tid + i * 256;           // 0..1023 = row*8 + j (j = int4 group)
        int row = idx >> 3, j = idx & 7;
        int4 v = *reinterpret_cast<const int4*>(
            pw + (size_t)(nb * 128 + row) * (K_DIM / 2) + kc * 32 + j * 4);
        smb[row * 32 + j * 4 + 0] = (uint8_t)v.x;
        smb[row * 32 + j * 4 + 1] = (uint8_t)v.y;
        smb[row * 32 + j * 4 + 2] = (uint8_t)v.z;
        smb[row * 32 + j * 4 + 3] = (uint8_t)v.w;
    }
    __syncthreads();

    // emit: word (p, kh, lane); 4 words per thread
    uint32_t* dst = g_wp + ((size_t)nb * K_CHUNKS + kc) * B_CHUNK_WORDS;
#pragma unroll
    for (int i = 0; i < 4; i++) {
        int o = tid + i * 256;             // 0..1023 = p*64 + kh*32 + lane
        int lane = o & 31, kh = (o >> 5) & 1, p = o >> 6;
        int row = p * 8 + (lane >> 2);
        int bcol = lane & 3;
        uint32_t wout = 0;
#pragma unroll
        for (int t = 0; t < 4; t++) {
            uint32_t B = smb[row * 32 + kh * 16 + 4 * t + bcol];
            wout |= (B & 0xFu) << (4 * t);          // lo nibble -> bits[4t+3:4t]
            wout |= (B >> 4) << (16 + 4 * t);       // hi nibble -> bits[16+4t..]
        }
        dst[o] = wout ^ 0x88888888u;                // nibble ^8 (offset-binary)
    }
}

// ---------------- GEMM: out = x' @ w4^T + (bias - c) ----------------
// 128 threads, 4 warps (2m x 2n), warp tile 64x64, 2 CTAs per SM, grid launch
__global__ void __launch_bounds__(128, 2) gemm_kernel(const float* __restrict__ bias,
                                                      float* __restrict__ out) {
    extern __shared__ char smem[];
    const uint32_t sb = smem_u32(smem);
    const int tid = threadIdx.x;
    const int lane = tid & 31;
    const int wid = tid >> 5;
    const int wm = wid >> 1;               // 0..1
    const int wn = wid & 1;                // 0..1

    const int bid = blockIdx.x;
    const int nb = bid / M_TILES;          // m fastest: co-resident CTAs share B panel
    const int mb = bid % M_TILES;

    const __half* gA = g_xs + (size_t)mb * K_CHUNKS * A_CHUNK_HALFS;
    const uint32_t* gB = g_wp + (size_t)nb * K_CHUNKS * B_CHUNK_WORDS;

    if (tid == 0) {
#pragma unroll
        for (int s = 0; s < STAGES; s++) {
            MBAR_INIT(sb + SM_FULL + 8 * s, 1);
            MBAR_INIT(sb + SM_EMPTY + 8 * s, 4);
        }
        asm volatile("fence.mbarrier_init.release.cluster;" ::: "memory");
    }
    __syncthreads();

    // initial fill: stage s owned by warp s, lane 0
    if (wid < STAGES && lane == 0) {
        const int s = wid;
        MBAR_EXPECT_TX(sb + SM_FULL + 8 * s, CHUNK_BYTES);
        BULK_G2S(sb + SM_A + s * A_STAGE_BYTES, gA + (size_t)s * A_CHUNK_HALFS, A_STAGE_BYTES, sb + SM_FULL + 8 * s);
        BULK_G2S(sb + SM_B + s * B_STAGE_BYTES, gB + (size_t)s * B_CHUNK_WORDS, B_STAGE_BYTES, sb + SM_FULL + 8 * s);
    }

    float acc[4][8][4];
#pragma unroll
    for (int a = 0; a < 4; a++)
#pragma unroll
        for (int b = 0; b < 8; b++)
#pragma unroll
            for (int d = 0; d < 4; d++) acc[a][b][d] = 0.f;

    int s = 0, ph = 0;
    for (int it = 0; it < K_CHUNKS; ++it) {
        MBAR_WAIT(sb + SM_FULL + 8 * s, ph);

        const uint4* As = reinterpret_cast<const uint4*>(smem + SM_A + s * A_STAGE_BYTES);
        const uint32_t* Bs = reinterpret_cast<const uint32_t*>(smem + SM_B + s * B_STAGE_BYTES);

#pragma unroll
        for (int kh = 0; kh < 2; kh++) {
            uint4 af[4][2];
#pragma unroll
            for (int mt = 0; mt < 4; mt++)
#pragma unroll
                for (int ks = 0; ks < 2; ks++)
                    af[mt][ks] = As[((wm * 4 + mt) * 4 + kh * 2 + ks) * 32 + lane];

#pragma unroll
            for (int jj = 0; jj < 8; jj++) {
                const int p = wn * 8 + jj;
                const uint32_t wb = Bs[(p * 2 + kh) * 32 + lane];
                const uint32_t b0 = dec4(wb, 0);    // ks 2kh:   k=c2,c2+1
                const uint32_t b1 = dec4(wb, 4);    // ks 2kh:   k=c2+8,c2+9
                const uint32_t b2 = dec4(wb, 8);    // ks 2kh+1: k=16+c2,..
                const uint32_t b3 = dec4(wb, 12);   // ks 2kh+1: k=24+c2,..
#pragma unroll
                for (int mt = 0; mt < 4; mt++) {
                    MMA_F16(acc[mt][jj], reinterpret_cast<const uint32_t*>(&af[mt][0]), b0, b1);
                    MMA_F16(acc[mt][jj], reinterpret_cast<const uint32_t*>(&af[mt][1]), b2, b3);
                }
            }
        }
        __syncwarp();
        if (lane == 0) MBAR_ARRIVE(sb + SM_EMPTY + 8 * s);

        // distributed refill: owner of stage s loads chunk it+STAGES
        if (wid == s && lane == 0 && it + STAGES < K_CHUNKS) {
            MBAR_WAIT(sb + SM_EMPTY + 8 * s, ph);
            MBAR_EXPECT_TX(sb + SM_FULL + 8 * s, CHUNK_BYTES);
            BULK_G2S(sb + SM_A + s * A_STAGE_BYTES, gA + (size_t)(it + STAGES) * A_CHUNK_HALFS, A_STAGE_BYTES, sb + SM_FULL + 8 * s);
            BULK_G2S(sb + SM_B + s * B_STAGE_BYTES, gB + (size_t)(it + STAGES) * B_CHUNK_WORDS, B_STAGE_BYTES, sb + SM_FULL + 8 * s);
        }
        if (++s == STAGES) { s = 0; ph ^= 1; }
    }

    // ---- epilogue: out = acc + bias[n] - c[m] ----
    const int c0 = (lane & 3) * 2;
    const int r0 = lane >> 2;
    const int ncol = nb * TILE_N + wn * 64 + c0;
    float2 bv[8];
#pragma unroll
    for (int jj = 0; jj < 8; jj++) bv[jj] = *reinterpret_cast<const float2*>(bias + ncol + jj * 8);

    const int mrow = mb * 128 + wm * 64 + r0;
#pragma unroll
    for (int mt = 0; mt < 4; mt++) {
#pragma unroll
        for (int h = 0; h < 2; h++) {
            const float cmv = g_c[mrow + mt * 16 + h * 8];
            float* orow = out + (size_t)(mrow + mt * 16 + h * 8) * N_DIM + ncol;
#pragma unroll
            for (int jj = 0; jj < 8; jj++) {
                float2 v;
                v.x = acc[mt][jj][h * 2 + 0] + bv[jj].x - cmv;
                v.y = acc[mt][jj][h * 2 + 1] + bv[jj].y - cmv;
                *reinterpret_cast<float2*>(orow + jj * 8) = v;
            }
        }
    }
}

// ---------------- host ----------------
extern "C" void kernel_launch(void* const* d_in, const int* in_sizes, int n_in,
                              void* d_out, int out_size) {
    const float* x      = (const float*)d_in[0];
    const int*   pw     = (const int*)d_in[1];
    const float* scales = (const float*)d_in[2];
    const float* zps    = (const float*)d_in[3];
    const float* bias   = (const float*)d_in[4];
    float* out = (float*)d_out;

    cudaFuncSetAttribute(gemm_kernel, cudaFuncAttributeMaxDynamicSharedMemorySize, SMEM_BYTES);

    prep_x_kernel<<<dim3(128, M_TILES), 256>>>(x, scales, zps);
    prep_wp_kernel<<<dim3(K_CHUNKS, N_TILES), 256>>>(pw);
    reduce_c_kernel<<<M_DIM / 256, 256>>>();
    gemm_kernel<<<NTILES, 128, SMEM_BYTES>>>(bias, out);
}

// round 16
// speedup vs baseline: 1.1727x; 1.1727x over previous
#include <cuda_runtime.h>
#include <cuda_fp16.h>
#include <cstdint>

// ---------------- problem dims ----------------
#define M_DIM 4096
#define K_DIM 4096
#define N_DIM 11008

#define TILE_M 128
#define TILE_N 128
#define TILE_K 64
#define STAGES 3
#define K_CHUNKS (K_DIM / TILE_K)      // 64
#define M_TILES (M_DIM / TILE_M)       // 32
#define N_TILES (N_DIM / TILE_N)       // 86
#define NTILES  (M_TILES * N_TILES)    // 2752

#define A_CHUNK_HALFS (TILE_M * TILE_K)       // 8192
#define B_CHUNK_HALFS (TILE_N * TILE_K)       // 8192
#define A_STAGE_BYTES (A_CHUNK_HALFS * 2)     // 16384
#define B_STAGE_BYTES (B_CHUNK_HALFS * 2)     // 16384
#define CHUNK_BYTES   (A_STAGE_BYTES + B_STAGE_BYTES)

#define SM_FULL  64
#define SM_EMPTY 128
#define SM_A     1024
#define SM_B     (SM_A + STAGES * A_STAGE_BYTES)       // 50176
#define SMEM_BYTES (SM_B + STAGES * B_STAGE_BYTES)     // 99328 (x2 CTAs = 198656)

// ---------------- scratch (device globals; allocation forbidden) ----------------
// A fragment-major: [mblock(32)][kchunk64(64)][bi(32)][lane(32)] uint4
//   bi = mtile(0..7)*4 + kstep(0..3).  lane's uint4 = a0..a3 of m16n8k16
//   (r=lane>>2, c2=(lane&3)*2):
//   (r,c2),(r,c2+1) | (r+8,c2),(r+8,c2+1) | (r,c2+8),(r,c2+9) | (r+8,c2+8),(r+8,c2+9)
__device__ __half g_xs[(size_t)M_DIM * K_DIM];
// B fp16 fragment-major: [nblock(86)][kchunk64(64)][p(16)*2 + kh(2)][lane(32)] uint4
//   p = n8 block; kh = 32-k granule within 64-k chunk; lane's uint4 =
//   {ks(2kh): b0,b1 | ks(2kh+1): b0,b1}, col n = p*8 + (lane>>2), c2=(lane&3)*2
__device__ __half g_w[(size_t)N_DIM * K_DIM];
__device__ float g_cp[(size_t)128 * M_DIM];   // partial c: [kc32][m]
__device__ float g_c[M_DIM];                  // c[m] = sum_k x[m,k]*s[g]*zp[g]

// ---------------- PTX helpers (generic features only) ----------------
__device__ __forceinline__ uint32_t smem_u32(const void* p) {
    uint32_t a;
    asm("{ .reg .u64 t; cvta.to.shared.u64 t, %1; cvt.u32.u64 %0, t; }" : "=r"(a) : "l"(p));
    return a;
}

#define MBAR_INIT(addr, cnt) \
    asm volatile("mbarrier.init.shared.b64 [%0], %1;" :: "r"(addr), "r"((uint32_t)(cnt)) : "memory")
#define MBAR_EXPECT_TX(addr, bytes) \
    asm volatile("mbarrier.arrive.expect_tx.shared.b64 _, [%0], %1;" :: "r"(addr), "r"((uint32_t)(bytes)) : "memory")
#define MBAR_ARRIVE(addr) \
    asm volatile("mbarrier.arrive.shared.b64 _, [%0];" :: "r"(addr) : "memory")

#define MBAR_WAIT(addr, parity) do {                                              \
    uint32_t _m = (addr); uint32_t _p = (parity); uint32_t _done;                 \
    asm volatile("{ .reg .pred p;"                                                \
        " mbarrier.try_wait.parity.shared.b64 p, [%1], %2;"                       \
        " selp.b32 %0, 1, 0, p; }" : "=r"(_done) : "r"(_m), "r"(_p) : "memory");  \
    if (!_done) {                                                                 \
        asm volatile("{ .reg .pred P1;"                                           \
            " WL_%=:"                                                             \
            " mbarrier.try_wait.parity.shared.b64 P1, [%0], %1;"                  \
            " @P1 bra.uni WD_%=;"                                                 \
            " bra.uni WL_%=;"                                                     \
            " WD_%=: }" :: "r"(_m), "r"(_p) : "memory");                          \
    }                                                                             \
} while (0)

#define BULK_G2S(dst, src, bytes, mbar)                                           \
    asm volatile("cp.async.bulk.shared::cluster.global.mbarrier::complete_tx::bytes " \
                 "[%0], [%1], %2, [%3];"                                          \
                 :: "r"(dst), "l"(src), "r"((uint32_t)(bytes)), "r"(mbar) : "memory")

#define MMA_F16(acc, au, b0, b1)                                                  \
    asm volatile("mma.sync.aligned.m16n8k16.row.col.f32.f16.f16.f32 "             \
        "{%0,%1,%2,%3}, {%4,%5,%6,%7}, {%8,%9}, {%0,%1,%2,%3};"                   \
        : "+f"((acc)[0]), "+f"((acc)[1]), "+f"((acc)[2]), "+f"((acc)[3])          \
        : "r"((au)[0]), "r"((au)[1]), "r"((au)[2]), "r"((au)[3]),                 \
          "r"(b0), "r"(b1))

__device__ __forceinline__ uint32_t h2u(float lo, float hi) {
    __half2 h = __floats2half2_rn(lo, hi);
    return *reinterpret_cast<uint32_t*>(&h);
}

// decode one packed byte -> half2((lo^8)-8, (hi^8)-8)  == signed int4 pair, exact.
// XOR 8 first (offset-binary), then (nib|0x6400) - 0x6408 per half.
__device__ __forceinline__ uint32_t dech2(uint32_t B) {
    uint32_t Bx = B ^ 0x88u;
    uint32_t r = (Bx & 0xFu) | ((Bx & 0xF0u) << 12) | 0x64006400u;  // (1024+lo', 1024+hi')
    __half2 h = *reinterpret_cast<__half2*>(&r);
    const uint32_t cu = 0x64086408u;                                // half2(1032, 1032)
    __half2 c = *reinterpret_cast<const __half2*>(&cu);
    __half2 v = __hsub2(h, c);
    return *reinterpret_cast<uint32_t*>(&v);
}

// ---------------- prep: x' = fp16(x*s) frag-major + partial c ----------------
__global__ void __launch_bounds__(256) prep_x_kernel(const float* __restrict__ x,
                                                     const float* __restrict__ scales,
                                                     const float* __restrict__ zps) {
    const int kc = blockIdx.x;             // 32-k granule 0..127
    const int mb = blockIdx.y;
    const int tid = threadIdx.x;
    __shared__ float sm[TILE_M * 33];      // 128x32, padded (conflict-free rows)

    const float s = scales[kc >> 1];       // group = 64 elems = 2 granules
    const float* xsrc = x + (size_t)mb * 128 * K_DIM + kc * 32;
#pragma unroll
    for (int i = 0; i < 16; i++) {
        int idx = tid + i * 256;
        int row = idx >> 5, col = idx & 31;
        sm[row * 33 + col] = xsrc[(size_t)row * K_DIM + col] * s;
    }
    __syncthreads();

    if (tid < 128) {
        float a = 0.f;
#pragma unroll
        for (int i = 0; i < 32; i++) a += sm[tid * 33 + i];
        g_cp[(size_t)kc * M_DIM + mb * 128 + tid] = a * zps[kc >> 1];
    }

    const int lane = tid & 31, w = tid >> 5;
    uint4* dst = reinterpret_cast<uint4*>(
        g_xs + ((size_t)mb * K_CHUNKS + (kc >> 1)) * A_CHUNK_HALFS);
    const int r = lane >> 2, c2 = (lane & 3) * 2;
    const int khalf = (kc & 1) * 2;        // kstep offset within 64-k chunk
#pragma unroll
    for (int i = 0; i < 2; i++) {
        int blk = w * 2 + i;               // 0..15
        int mt = blk >> 1, ks = blk & 1;
        int rr = mt * 16 + r;
        int k0 = ks * 16 + c2;
        uint4 v;
        v.x = h2u(sm[rr * 33 + k0],           sm[rr * 33 + k0 + 1]);
        v.y = h2u(sm[(rr + 8) * 33 + k0],     sm[(rr + 8) * 33 + k0 + 1]);
        v.z = h2u(sm[rr * 33 + k0 + 8],       sm[rr * 33 + k0 + 9]);
        v.w = h2u(sm[(rr + 8) * 33 + k0 + 8], sm[(rr + 8) * 33 + k0 + 9]);
        dst[(mt * 4 + khalf + ks) * 32 + lane] = v;
    }
}

// ---------------- prep: reduce partial c (fixed order -> deterministic) ----------------
__global__ void __launch_bounds__(256) reduce_c_kernel() {
    const int m = blockIdx.x * 256 + threadIdx.x;
    float a = 0.f;
#pragma unroll 8
    for (int kc = 0; kc < 128; kc++) a += g_cp[(size_t)kc * M_DIM + m];
    g_c[m] = a;
}

// ---------------- prep: int4 -> fp16 frag-major, direct register path ----------------
// packed_w: (N, K/2) int32, ONE byte per element (row stride 2048 int32).
// Thread = (row 0..127, kh 0..1). Reads the granule's 16 bytes (as 16 int32 via
// 4x LDG.128), decodes, writes 4 consecutive uint4 (lanes (row&7)*4 .. +3).
// For lane slot bc (= lane&3): v.x <- byte bc (k=c2,c2+1), v.y <- byte 4+bc
// (k=c2+8,c2+9), v.z <- byte 8+bc (16+c2..), v.w <- byte 12+bc (24+c2..).
__global__ void __launch_bounds__(256) prep_w_kernel(const int* __restrict__ pw) {
    const int kc = blockIdx.x;             // 64-k chunk 0..63
    const int nb = blockIdx.y;             // nblock 0..85
    const int tid = threadIdx.x;
    const int row = tid >> 1;              // 0..127
    const int kh = tid & 1;

    const int* src = pw + (size_t)(nb * 128 + row) * (K_DIM / 2) + kc * 32 + kh * 16;
    uint32_t b[16];
#pragma unroll
    for (int i = 0; i < 4; i++) {
        int4 v = reinterpret_cast<const int4*>(src)[i];
        b[i * 4 + 0] = (uint32_t)v.x; b[i * 4 + 1] = (uint32_t)v.y;
        b[i * 4 + 2] = (uint32_t)v.z; b[i * 4 + 3] = (uint32_t)v.w;
    }

    uint4* dst = reinterpret_cast<uint4*>(g_w + ((size_t)nb * K_CHUNKS + kc) * B_CHUNK_HALFS)
                 + (((row >> 3) * 2 + kh) * 32 + (row & 7) * 4);
#pragma unroll
    for (int bc = 0; bc < 4; bc++) {
        uint4 o;
        o.x = dech2(b[bc]);
        o.y = dech2(b[4 + bc]);
        o.z = dech2(b[8 + bc]);
        o.w = dech2(b[12 + bc]);
        dst[bc] = o;
    }
}

// ---------------- GEMM (R9 champion): out = x' @ w4^T + (bias - c) ----------------
// 128 threads, 4 warps (2m x 2n), warp tile 64x64, 2 CTAs per SM, grid launch
__global__ void __launch_bounds__(128, 2) gemm_kernel(const float* __restrict__ bias,
                                                      float* __restrict__ out) {
    extern __shared__ char smem[];
    const uint32_t sb = smem_u32(smem);
    const int tid = threadIdx.x;
    const int lane = tid & 31;
    const int wid = tid >> 5;
    const int wm = wid >> 1;               // 0..1
    const int wn = wid & 1;                // 0..1

    const int bid = blockIdx.x;
    const int nb = bid / M_TILES;          // m fastest: co-resident CTAs share B panel
    const int mb = bid % M_TILES;

    const __half* gA = g_xs + (size_t)mb * K_CHUNKS * A_CHUNK_HALFS;
    const __half* gB = g_w + (size_t)nb * K_CHUNKS * B_CHUNK_HALFS;

    if (tid == 0) {
#pragma unroll
        for (int s = 0; s < STAGES; s++) {
            MBAR_INIT(sb + SM_FULL + 8 * s, 1);
            MBAR_INIT(sb + SM_EMPTY + 8 * s, 4);
        }
        asm volatile("fence.mbarrier_init.release.cluster;" ::: "memory");
    }
    __syncthreads();

    // initial fill: stage s owned by warp s, lane 0
    if (wid < STAGES && lane == 0) {
        const int s = wid;
        MBAR_EXPECT_TX(sb + SM_FULL + 8 * s, CHUNK_BYTES);
        BULK_G2S(sb + SM_A + s * A_STAGE_BYTES, gA + (size_t)s * A_CHUNK_HALFS, A_STAGE_BYTES, sb + SM_FULL + 8 * s);
        BULK_G2S(sb + SM_B + s * B_STAGE_BYTES, gB + (size_t)s * B_CHUNK_HALFS, B_STAGE_BYTES, sb + SM_FULL + 8 * s);
    }

    float acc[4][8][4];
#pragma unroll
    for (int a = 0; a < 4; a++)
#pragma unroll
        for (int b = 0; b < 8; b++)
#pragma unroll
            for (int d = 0; d < 4; d++) acc[a][b][d] = 0.f;

    int s = 0, ph = 0;
    for (int it = 0; it < K_CHUNKS; ++it) {
        MBAR_WAIT(sb + SM_FULL + 8 * s, ph);

        const uint4* As = reinterpret_cast<const uint4*>(smem + SM_A + s * A_STAGE_BYTES);
        const uint4* Bs = reinterpret_cast<const uint4*>(smem + SM_B + s * B_STAGE_BYTES);

#pragma unroll
        for (int kh = 0; kh < 2; kh++) {
            uint4 af[4][2];
#pragma unroll
            for (int mt = 0; mt < 4; mt++)
#pragma unroll
                for (int ks = 0; ks < 2; ks++)
                    af[mt][ks] = As[((wm * 4 + mt) * 4 + kh * 2 + ks) * 32 + lane];

#pragma unroll
            for (int jj = 0; jj < 8; jj++) {
                const int p = wn * 8 + jj;
                uint4 bj = Bs[(p * 2 + kh) * 32 + lane];   // ksteps 2kh, 2kh+1
#pragma unroll
                for (int mt = 0; mt < 4; mt++) {
                    MMA_F16(acc[mt][jj], reinterpret_cast<const uint32_t*>(&af[mt][0]), bj.x, bj.y);
                    MMA_F16(acc[mt][jj], reinterpret_cast<const uint32_t*>(&af[mt][1]), bj.z, bj.w);
                }
            }
        }
        __syncwarp();
        if (lane == 0) MBAR_ARRIVE(sb + SM_EMPTY + 8 * s);

        // distributed refill: owner of stage s loads chunk it+STAGES
        if (wid == s && lane == 0 && it + STAGES < K_CHUNKS) {
            MBAR_WAIT(sb + SM_EMPTY + 8 * s, ph);
            MBAR_EXPECT_TX(sb + SM_FULL + 8 * s, CHUNK_BYTES);
            BULK_G2S(sb + SM_A + s * A_STAGE_BYTES, gA + (size_t)(it + STAGES) * A_CHUNK_HALFS, A_STAGE_BYTES, sb + SM_FULL + 8 * s);
            BULK_G2S(sb + SM_B + s * B_STAGE_BYTES, gB + (size_t)(it + STAGES) * B_CHUNK_HALFS, B_STAGE_BYTES, sb + SM_FULL + 8 * s);
        }
        if (++s == STAGES) { s = 0; ph ^= 1; }
    }

    // ---- epilogue: out = acc + bias[n] - c[m] ----
    const int c0 = (lane & 3) * 2;
    const int r0 = lane >> 2;
    const int ncol = nb * TILE_N + wn * 64 + c0;
    float2 bv[8];
#pragma unroll
    for (int jj = 0; jj < 8; jj++) bv[jj] = *reinterpret_cast<const float2*>(bias + ncol + jj * 8);

    const int mrow = mb * 128 + wm * 64 + r0;
#pragma unroll
    for (int mt = 0; mt < 4; mt++) {
#pragma unroll
        for (int h = 0; h < 2; h++) {
            const float cmv = g_c[mrow + mt * 16 + h * 8];
            float* orow = out + (size_t)(mrow + mt * 16 + h * 8) * N_DIM + ncol;
#pragma unroll
            for (int jj = 0; jj < 8; jj++) {
                float2 v;
                v.x = acc[mt][jj][h * 2 + 0] + bv[jj].x - cmv;
                v.y = acc[mt][jj][h * 2 + 1] + bv[jj].y - cmv;
                *reinterpret_cast<float2*>(orow + jj * 8) = v;
            }
        }
    }
}

// ---------------- host ----------------
extern "C" void kernel_launch(void* const* d_in, const int* in_sizes, int n_in,
                              void* d_out, int out_size) {
    const float* x      = (const float*)d_in[0];
    const int*   pw     = (const int*)d_in[1];
    const float* scales = (const float*)d_in[2];
    const float* zps    = (const float*)d_in[3];
    const float* bias   = (const float*)d_in[4];
    float* out = (float*)d_out;

    cudaFuncSetAttribute(gemm_kernel, cudaFuncAttributeMaxDynamicSharedMemorySize, SMEM_BYTES);

    prep_x_kernel<<<dim3(128, M_TILES), 256>>>(x, scales, zps);
    prep_w_kernel<<<dim3(K_CHUNKS, N_TILES), 256>>>(pw);
    reduce_c_kernel<<<M_DIM / 256, 256>>>();
    gemm_kernel<<<NTILES, 128, SMEM_BYTES>>>(bias, out);
}